// round 9
// baseline (speedup 1.0000x reference)
#include <cuda_runtime.h>
#include <cstdint>

// B=2048, D=3706, total=B*D=7,589,888 (divisible by 256)
// inputs: d_in[0] fake [B,D] f32; d_in[1] minb [D] f32; d_in[2] lens [D,4] f32
// output: dist f32 [B,D,6] then val f32 [B,D]
//
// b0=min[d]; b_{k+1}=b_k+relu(len[d,k])+1e-4 (strictly increasing)
// dist[r] = (r==0 || a>b[r-1]) && (r==5 || a<b[r]); a==b_k -> all zeros
// val = sum r*dist[r]
//
// R9 = R4 (smem-staged dist, coalesced float4 __stcs flush, TPB=256,
// fake default-policy -> L2-resident across graph replays) plus:
//   - idx % D via PROVEN magic division:
//       magic = floor(2^40 / D) + 1, f = magic*D - 2^40 <= D,
//       q = (x * magic) >> 40 exact for x < 2^40/f >= 2^40/D ~ 2.97e8 >> total.
//   - val staged in smem, flushed as float4 __stcs.

#define EPSK 1e-4f
#define TPB 256
#define MAGIC_K 40

__global__ void __launch_bounds__(TPB)
discret_kernel(const float* __restrict__ fake,
               const float* __restrict__ minb,
               const float4* __restrict__ lens,
               float* __restrict__ out_dist,   // [B*D*6]
               float* __restrict__ out_val,    // [B*D]
               int total, unsigned D,
               unsigned long long magic)
{
    __shared__ __align__(16) float sdist[TPB * 6];   // 6 KB
    __shared__ __align__(16) float sval[TPB];        // 1 KB

    int t   = threadIdx.x;
    int idx = blockIdx.x * TPB + t;

    float d0 = 0.f, d1 = 0.f, d2 = 0.f, d3 = 0.f, d4 = 0.f, d5 = 0.f;
    float v  = 0.f;

    if (idx < total) {
        // d = idx - D * floor(idx/D), floor via 64-bit magic multiply (exact, see header)
        unsigned x = (unsigned)idx;
        unsigned q = (unsigned)(((unsigned long long)x * magic) >> MAGIC_K);
        unsigned d = x - q * D;

        float a  = fake[idx];              // default policy: L2-resident across replays
        float4 L = __ldg(&lens[d]);
        float b0 = __ldg(&minb[d]);
        float b1 = b0 + fmaxf(L.x, 0.0f) + EPSK;
        float b2 = b1 + fmaxf(L.y, 0.0f) + EPSK;
        float b3 = b2 + fmaxf(L.z, 0.0f) + EPSK;
        float b4 = b3 + fmaxf(L.w, 0.0f) + EPSK;

        d0 = (a < b0)           ? 1.0f : 0.0f;
        d1 = (a > b0 && a < b1) ? 1.0f : 0.0f;
        d2 = (a > b1 && a < b2) ? 1.0f : 0.0f;
        d3 = (a > b2 && a < b3) ? 1.0f : 0.0f;
        d4 = (a > b3 && a < b4) ? 1.0f : 0.0f;
        d5 = (a > b4)           ? 1.0f : 0.0f;

        v = d1 + 2.0f * d2 + 3.0f * d3 + 4.0f * d4 + 5.0f * d5;
    }

    // stage (stride-6 word writes: benign 2-way bank conflict)
    float* s = sdist + t * 6;
    s[0] = d0; s[1] = d1; s[2] = d2; s[3] = d3; s[4] = d4; s[5] = d5;
    sval[t] = v;
    __syncthreads();

    int block_first = blockIdx.x * TPB;
    int n_valid = total - block_first;
    if (n_valid >= TPB) {
        // dist: 1536 floats = 384 float4, fully coalesced, evict-first
        const float4* s4 = reinterpret_cast<const float4*>(sdist);
        float4* g4 = reinterpret_cast<float4*>(out_dist + (size_t)block_first * 6);
        #pragma unroll
        for (int i = t; i < (TPB * 6) / 4; i += TPB)
            __stcs(&g4[i], s4[i]);

        // val: 256 floats = 64 float4, evict-first
        if (t < TPB / 4) {
            const float4* sv4 = reinterpret_cast<const float4*>(sval);
            float4* gv4 = reinterpret_cast<float4*>(out_val + (size_t)block_first);
            __stcs(&gv4[t], sv4[t]);
        }
    } else {
        // tail block (unused for this shape, kept for generality)
        float* g = out_dist + (size_t)block_first * 6;
        for (int i = t; i < n_valid * 6; i += TPB)
            __stcs(&g[i], sdist[i]);
        for (int i = t; i < n_valid; i += TPB)
            __stcs(&out_val[block_first + i], sval[i]);
    }
}

extern "C" void kernel_launch(void* const* d_in, const int* in_sizes, int n_in,
                              void* d_out, int out_size)
{
    const float*  fake = (const float*)d_in[0];
    const float*  minb = (const float*)d_in[1];
    const float4* lens = (const float4*)d_in[2];

    int total  = in_sizes[0];          // B*D
    unsigned D = (unsigned)in_sizes[1];

    // magic = floor(2^40 / D) + 1  (2^40 fits in u64; magic < 2^32 for D > 256)
    unsigned long long magic = ((1ull << MAGIC_K) / D) + 1ull;

    float* out  = (float*)d_out;
    float* dist = out;                          // [B*D*6]
    float* val  = out + (size_t)total * 6;      // [B*D]

    int blocks = (total + TPB - 1) / TPB;
    discret_kernel<<<blocks, TPB>>>(fake, minb, lens, dist, val, total, D, magic);
}

// round 10
// speedup vs baseline: 1.0428x; 1.0428x over previous
#include <cuda_runtime.h>
#include <cstdint>

// B=2048, D=3706, total=B*D=7,589,888 (divisible by 256)
// inputs: d_in[0] fake [B,D] f32; d_in[1] minb [D] f32; d_in[2] lens [D,4] f32
// output: dist f32 [B,D,6] then val f32 [B,D]
//
// b0=min[d]; b_{k+1}=b_k+relu(len[d,k])+1e-4 (strictly increasing)
// dist[r] = (r==0 || a>b[r-1]) && (r==5 || a<b[r]); a==b_k -> all zeros
// val = sum r*dist[r]
//
// R10 = R4 VERBATIM (best: 37.3us) with exactly one change:
//   idx % D -> proven magic division (magic = floor(2^40/D)+1, exact for
//   x < 2^40/D ~ 2.97e8 >> total; validated rel_err=0 in R9).
// Kept from R4: TPB=256, EARLY per-thread __stcs val store (overlaps compute),
// smem-staged dist flushed as coalesced float4 __stcs, fake default-policy
// (L2-resident across graph replays).

#define EPSK 1e-4f
#define TPB 256
#define MAGIC_K 40

__global__ void __launch_bounds__(TPB)
discret_kernel(const float* __restrict__ fake,
               const float* __restrict__ minb,
               const float4* __restrict__ lens,
               float* __restrict__ out_dist,   // [B*D*6]
               float* __restrict__ out_val,    // [B*D]
               int total, unsigned D,
               unsigned long long magic)
{
    __shared__ float sdist[TPB * 6];   // 6 KB

    int t   = threadIdx.x;
    int idx = blockIdx.x * TPB + t;

    float d0 = 0.f, d1 = 0.f, d2 = 0.f, d3 = 0.f, d4 = 0.f, d5 = 0.f;

    if (idx < total) {
        // d = idx - D*floor(idx/D) via exact magic multiply
        unsigned x = (unsigned)idx;
        unsigned q = (unsigned)(((unsigned long long)x * magic) >> MAGIC_K);
        unsigned d = x - q * D;

        float a  = fake[idx];              // default policy: L2-resident across replays
        float4 L = __ldg(&lens[d]);
        float b0 = __ldg(&minb[d]);
        float b1 = b0 + fmaxf(L.x, 0.0f) + EPSK;
        float b2 = b1 + fmaxf(L.y, 0.0f) + EPSK;
        float b3 = b2 + fmaxf(L.z, 0.0f) + EPSK;
        float b4 = b3 + fmaxf(L.w, 0.0f) + EPSK;

        d0 = (a < b0)           ? 1.0f : 0.0f;
        d1 = (a > b0 && a < b1) ? 1.0f : 0.0f;
        d2 = (a > b1 && a < b2) ? 1.0f : 0.0f;
        d3 = (a > b2 && a < b3) ? 1.0f : 0.0f;
        d4 = (a > b3 && a < b4) ? 1.0f : 0.0f;
        d5 = (a > b4)           ? 1.0f : 0.0f;

        float v = d1 + 2.0f * d2 + 3.0f * d3 + 4.0f * d4 + 5.0f * d5;
        __stcs(&out_val[idx], v);          // EARLY store, overlaps compute (R4 schedule)
    }

    // stage into smem (stride-6 word writes: benign 2-way bank conflict)
    float* s = sdist + t * 6;
    s[0] = d0; s[1] = d1; s[2] = d2; s[3] = d3; s[4] = d4; s[5] = d5;
    __syncthreads();

    int block_first = blockIdx.x * TPB;
    int n_valid = total - block_first;
    if (n_valid >= TPB) {
        // full block: flush 1536 floats = 384 float4, fully coalesced, evict-first
        const float4* s4 = reinterpret_cast<const float4*>(sdist);
        float4* g4 = reinterpret_cast<float4*>(out_dist + (size_t)block_first * 6);
        #pragma unroll
        for (int i = t; i < (TPB * 6) / 4; i += TPB)
            __stcs(&g4[i], s4[i]);
    } else {
        // tail block (unused for this shape, kept for generality)
        float* g = out_dist + (size_t)block_first * 6;
        for (int i = t; i < n_valid * 6; i += TPB)
            __stcs(&g[i], sdist[i]);
    }
}

extern "C" void kernel_launch(void* const* d_in, const int* in_sizes, int n_in,
                              void* d_out, int out_size)
{
    const float*  fake = (const float*)d_in[0];
    const float*  minb = (const float*)d_in[1];
    const float4* lens = (const float4*)d_in[2];

    int total  = in_sizes[0];          // B*D
    unsigned D = (unsigned)in_sizes[1];

    // magic = floor(2^40/D) + 1 ; exact q for all x in range (see header)
    unsigned long long magic = ((1ull << MAGIC_K) / D) + 1ull;

    float* out  = (float*)d_out;
    float* dist = out;                          // [B*D*6]
    float* val  = out + (size_t)total * 6;      // [B*D]

    int blocks = (total + TPB - 1) / TPB;
    discret_kernel<<<blocks, TPB>>>(fake, minb, lens, dist, val, total, D, magic);
}